// round 7
// baseline (speedup 1.0000x reference)
#include <cuda_runtime.h>
#include <cuda_fp16.h>

#define N_NODES 100000
#define IN_DIM  1024
#define OUT_DIM 256
#define NNZ_X   3200000
#define NNZ_ADJ 3200000

#define SCAN_B    1024
#define N_SCANBLK ((N_NODES + SCAN_B - 1) / SCAN_B)   // 98

// ---------------- scratch (__device__ globals; no allocs allowed) ----------
__device__ __half g_xw[(size_t)N_NODES * OUT_DIM];     // 51.2 MB (L2-resident)
__device__ __half g_wh[IN_DIM * OUT_DIM];              // 512 KB

// NOTE: counters rely on zero-init at module load + self-restoring property:
// hist adds each node's count, scatter atomicSub's it back to exactly 0.
__device__ int   g_counts_x[N_NODES];
__device__ int   g_counts_a[N_NODES];
__device__ int   g_offs_x[N_NODES + 1];
__device__ int   g_offs_a[N_NODES + 1];
__device__ int   g_bsums_x[N_SCANBLK];
__device__ int   g_bsums_a[N_SCANBLK];
__device__ int2  g_cx[NNZ_X];                          // (col, val-bits)
__device__ int2  g_ca[NNZ_ADJ];

// ---------------- W fp32 -> fp16 -------------------------------------------
__global__ void wcvt_kernel(const float* __restrict__ W, __half* __restrict__ Wh) {
    int i = blockIdx.x * blockDim.x + threadIdx.x;      // over float2 pairs
    if (i < IN_DIM * OUT_DIM / 2) {
        float2 w = __ldcs(reinterpret_cast<const float2*>(W) + i);
        reinterpret_cast<__half2*>(Wh)[i] = __floats2half2_rn(w.x, w.y);
    }
}

// ---------------- histogram of one row array --------------------------------
__global__ void hist_kernel(const int* __restrict__ rows, int* __restrict__ counts, int nnz) {
    int i = blockIdx.x * blockDim.x + threadIdx.x;
    if (i < nnz) atomicAdd(&counts[__ldcs(&rows[i])], 1);
}

// ---------------- scan A: per-block exclusive scan --------------------------
__global__ void scanA_kernel(const int* __restrict__ counts,
                             int* __restrict__ offs, int* __restrict__ bsums) {
    __shared__ int sm[SCAN_B];
    int t = threadIdx.x;
    int i = blockIdx.x * SCAN_B + t;
    int v = (i < N_NODES) ? counts[i] : 0;
    sm[t] = v;
    __syncthreads();
    for (int d = 1; d < SCAN_B; d <<= 1) {
        int add = (t >= d) ? sm[t - d] : 0;
        __syncthreads();
        sm[t] += add;
        __syncthreads();
    }
    int incl = sm[t];
    if (i < N_NODES) offs[i] = incl - v;
    if (t == SCAN_B - 1) bsums[blockIdx.x] = incl;     // inclusive block total
}

// ---------------- scan C: re-scan block sums in-block, add offsets ----------
__global__ void scanC_kernel(int* __restrict__ offs, const int* __restrict__ bsums, int total) {
    __shared__ int sb[128];
    int t = threadIdx.x;
    if (t < 128) sb[t] = (t < N_SCANBLK) ? bsums[t] : 0;
    __syncthreads();
    for (int d = 1; d < 128; d <<= 1) {
        int add = (t < 128 && t >= d) ? sb[t - d] : 0;
        __syncthreads();
        if (t < 128) sb[t] += add;
        __syncthreads();
    }
    int boff = (blockIdx.x == 0) ? 0 : sb[blockIdx.x - 1];
    int i = blockIdx.x * SCAN_B + t;
    if (i < N_NODES) offs[i] += boff;
    if (i == 0) offs[N_NODES] = total;
}

// ---------------- scatter COO -> CSR (int2 payload) --------------------------
// counts[] holds the histogram; atomicSub drains it back to 0 (self-restoring).
__global__ void scatter_kernel(const int* __restrict__ rows, const int* __restrict__ cols,
                               const float* __restrict__ vals,
                               const int* __restrict__ offs, int* __restrict__ cnt,
                               int2* __restrict__ cdata, int nnz) {
    int i = blockIdx.x * blockDim.x + threadIdx.x;
    if (i >= nnz) return;
    int r = __ldcs(&rows[i]);
    int p = offs[r] + atomicSub(&cnt[r], 1) - 1;
    cdata[p] = make_int2(__ldcs(&cols[i]), __float_as_int(__ldcs(&vals[i])));
}

// ---------------- SpMM1: 2 column-half passes; W half (256KB) L1-resident ---
// grid = (row_blocks, 2). Lane j owns cols [c0+4j, c0+4j+4): one LDG.64 per nnz.
__global__ void __launch_bounds__(256, 8)
spmm1_kernel(const int* __restrict__ offs, const int2* __restrict__ cdata,
             const __half* __restrict__ Wh, __half* __restrict__ xw) {
    int warp = (blockIdx.x * blockDim.x + threadIdx.x) >> 5;
    int lane = threadIdx.x & 31;
    if (warp >= N_NODES) return;
    int c0 = blockIdx.y * 128;                         // column half base

    int beg = offs[warp];
    int end = offs[warp + 1];

    float a0 = 0.f, a1 = 0.f, a2 = 0.f, a3 = 0.f;

    for (int base = beg; base < end; base += 32) {
        int k = base + lane;
        int2 cv = (k < end) ? __ldcs(&cdata[k]) : make_int2(0, 0);
        int m = min(32, end - base);
        for (int t = 0; t < m; t++) {
            int   cc = __shfl_sync(0xffffffffu, cv.x, t);
            float vv = __int_as_float(__shfl_sync(0xffffffffu, cv.y, t));
            int2 wv = __ldg(reinterpret_cast<const int2*>(Wh + (size_t)cc * OUT_DIM + c0) + lane);
            float2 f0 = __half22float2(*reinterpret_cast<__half2*>(&wv.x));
            float2 f1 = __half22float2(*reinterpret_cast<__half2*>(&wv.y));
            a0 = fmaf(vv, f0.x, a0); a1 = fmaf(vv, f0.y, a1);
            a2 = fmaf(vv, f1.x, a2); a3 = fmaf(vv, f1.y, a3);
        }
    }

    int2 o;
    __half2 h0 = __floats2half2_rn(a0, a1);
    __half2 h1 = __floats2half2_rn(a2, a3);
    o.x = *reinterpret_cast<int*>(&h0);
    o.y = *reinterpret_cast<int*>(&h1);
    reinterpret_cast<int2*>(xw + (size_t)warp * OUT_DIM + c0)[lane] = o;
}

// ---------------- SpMM2 + ReLU: streaming stores protect xw in L2 -----------
__global__ void __launch_bounds__(256, 8)
spmm2_kernel(const int* __restrict__ offs, const int2* __restrict__ cdata,
             const __half* __restrict__ xw, float* __restrict__ out) {
    int warp = (blockIdx.x * blockDim.x + threadIdx.x) >> 5;
    int lane = threadIdx.x & 31;
    if (warp >= N_NODES) return;

    int beg = offs[warp];
    int end = offs[warp + 1];

    float a0 = 0.f, a1 = 0.f, a2 = 0.f, a3 = 0.f;
    float a4 = 0.f, a5 = 0.f, a6 = 0.f, a7 = 0.f;

    for (int base = beg; base < end; base += 32) {
        int k = base + lane;
        int2 cv = (k < end) ? __ldcs(&cdata[k]) : make_int2(0, 0);
        int m = min(32, end - base);
        for (int t = 0; t < m; t++) {
            int   cc = __shfl_sync(0xffffffffu, cv.x, t);
            float vv = __int_as_float(__shfl_sync(0xffffffffu, cv.y, t));
            int4 wv = __ldg(reinterpret_cast<const int4*>(xw + (size_t)cc * OUT_DIM) + lane);
            float2 f0 = __half22float2(*reinterpret_cast<__half2*>(&wv.x));
            float2 f1 = __half22float2(*reinterpret_cast<__half2*>(&wv.y));
            float2 f2 = __half22float2(*reinterpret_cast<__half2*>(&wv.z));
            float2 f3 = __half22float2(*reinterpret_cast<__half2*>(&wv.w));
            a0 = fmaf(vv, f0.x, a0); a1 = fmaf(vv, f0.y, a1);
            a2 = fmaf(vv, f1.x, a2); a3 = fmaf(vv, f1.y, a3);
            a4 = fmaf(vv, f2.x, a4); a5 = fmaf(vv, f2.y, a5);
            a6 = fmaf(vv, f3.x, a6); a7 = fmaf(vv, f3.y, a7);
        }
    }

    float4* d = reinterpret_cast<float4*>(out + (size_t)warp * OUT_DIM) + lane * 2;
    __stcs(d,     make_float4(fmaxf(a0, 0.f), fmaxf(a1, 0.f), fmaxf(a2, 0.f), fmaxf(a3, 0.f)));
    __stcs(d + 1, make_float4(fmaxf(a4, 0.f), fmaxf(a5, 0.f), fmaxf(a6, 0.f), fmaxf(a7, 0.f)));
}

// ---------------------------------------------------------------------------
extern "C" void kernel_launch(void* const* d_in, const int* in_sizes, int n_in,
                              void* d_out, int out_size) {
    const int*   x_rows   = (const int*)  d_in[0];
    const int*   x_cols   = (const int*)  d_in[1];
    const float* x_vals   = (const float*)d_in[2];
    const int*   adj_rows = (const int*)  d_in[3];
    const int*   adj_cols = (const int*)  d_in[4];
    const float* adj_vals = (const float*)d_in[5];
    const float* W        = (const float*)d_in[6];
    float*       out      = (float*)d_out;

    __half *xw, *Wh; int *cntx, *cnta, *ox, *oa, *bx, *ba; int2 *cx, *ca;
    cudaGetSymbolAddress((void**)&xw,   g_xw);
    cudaGetSymbolAddress((void**)&Wh,   g_wh);
    cudaGetSymbolAddress((void**)&cntx, g_counts_x);
    cudaGetSymbolAddress((void**)&cnta, g_counts_a);
    cudaGetSymbolAddress((void**)&ox,   g_offs_x);
    cudaGetSymbolAddress((void**)&oa,   g_offs_a);
    cudaGetSymbolAddress((void**)&bx,   g_bsums_x);
    cudaGetSymbolAddress((void**)&ba,   g_bsums_a);
    cudaGetSymbolAddress((void**)&cx,   g_cx);
    cudaGetSymbolAddress((void**)&ca,   g_ca);

    // Side stream + events: created once on first (uncaptured) call, reused.
    static cudaStream_t s2 = nullptr;
    static cudaEvent_t  evFork = nullptr, evJoin = nullptr, evW = nullptr;
    if (s2 == nullptr) {
        cudaStreamCreateWithFlags(&s2, cudaStreamNonBlocking);
        cudaEventCreateWithFlags(&evFork, cudaEventDisableTiming);
        cudaEventCreateWithFlags(&evJoin, cudaEventDisableTiming);
        cudaEventCreateWithFlags(&evW,    cudaEventDisableTiming);
    }

    const int nnz_blocks = (NNZ_X + 255) / 256;

    // ---- fork (counters are self-zeroed; no zero pass needed) ----
    cudaEventRecord(evFork, 0);
    cudaStreamWaitEvent(s2, evFork, 0);

    // ---- chain B (W convert + adj build) on side stream ----
    wcvt_kernel<<<(IN_DIM * OUT_DIM / 2 + 255) / 256, 256, 0, s2>>>(W, Wh);
    cudaEventRecord(evW, s2);                       // spmm1 depends on Wh
    hist_kernel<<<nnz_blocks, 256, 0, s2>>>(adj_rows, cnta, NNZ_ADJ);
    scanA_kernel<<<N_SCANBLK, SCAN_B, 0, s2>>>(cnta, oa, ba);
    scanC_kernel<<<N_SCANBLK, SCAN_B, 0, s2>>>(oa, ba, NNZ_ADJ);
    scatter_kernel<<<nnz_blocks, 256, 0, s2>>>(adj_rows, adj_cols, adj_vals,
                                               oa, cnta, ca, NNZ_ADJ);
    cudaEventRecord(evJoin, s2);

    // ---- chain A (x build + spmm1) on main stream ----
    hist_kernel<<<nnz_blocks, 256>>>(x_rows, cntx, NNZ_X);
    scanA_kernel<<<N_SCANBLK, SCAN_B>>>(cntx, ox, bx);
    scanC_kernel<<<N_SCANBLK, SCAN_B>>>(ox, bx, NNZ_X);
    scatter_kernel<<<nnz_blocks, 256>>>(x_rows, x_cols, x_vals,
                                        ox, cntx, cx, NNZ_X);

    cudaStreamWaitEvent(0, evW, 0);                 // ensure Wh ready (race fix)
    const int spmm_blocks = (N_NODES * 32 + 255) / 256;   // warp per row
    spmm1_kernel<<<dim3(spmm_blocks, 2), 256>>>(ox, cx, Wh, xw);

    // ---- join, then SpMM2 + ReLU ----
    cudaStreamWaitEvent(0, evJoin, 0);
    spmm2_kernel<<<spmm_blocks, 256>>>(oa, ca, xw, out);
}

// round 8
// speedup vs baseline: 1.0719x; 1.0719x over previous
#include <cuda_runtime.h>
#include <cuda_fp16.h>

#define N_NODES 100000
#define IN_DIM  1024
#define OUT_DIM 256
#define NNZ_X   3200000
#define NNZ_ADJ 3200000

#define SCAN_B    1024
#define N_SCANBLK ((N_NODES + SCAN_B - 1) / SCAN_B)   // 98

// ---------------- scratch (__device__ globals; no allocs allowed) ----------
__device__ __half g_xw[(size_t)N_NODES * OUT_DIM];     // 51.2 MB (L2-resident)
__device__ __half g_wh[IN_DIM * OUT_DIM];              // 512 KB

// Counters rely on zero-init at module load + self-restoring property:
// hist adds each node's count, scatter atomicSub's it back to exactly 0.
__device__ int   g_counts_x[N_NODES];
__device__ int   g_counts_a[N_NODES];
__device__ int   g_offs_x[N_NODES + 1];
__device__ int   g_offs_a[N_NODES + 1];
__device__ int   g_bsums_x[N_SCANBLK];
__device__ int   g_bsums_a[N_SCANBLK];
__device__ int2  g_cx[NNZ_X];                          // (col, val-bits)
__device__ int2  g_ca[NNZ_ADJ];

// ---------------- W fp32 -> fp16 -------------------------------------------
__global__ void wcvt_kernel(const float* __restrict__ W, __half* __restrict__ Wh) {
    int i = blockIdx.x * blockDim.x + threadIdx.x;      // over float2 pairs
    if (i < IN_DIM * OUT_DIM / 2) {
        float2 w = __ldcs(reinterpret_cast<const float2*>(W) + i);
        reinterpret_cast<__half2*>(Wh)[i] = __floats2half2_rn(w.x, w.y);
    }
}

// ---------------- histogram of one row array --------------------------------
__global__ void hist_kernel(const int* __restrict__ rows, int* __restrict__ counts, int nnz) {
    int i = blockIdx.x * blockDim.x + threadIdx.x;
    if (i < nnz) atomicAdd(&counts[__ldcs(&rows[i])], 1);
}

// ---------------- scan A: per-block exclusive scan --------------------------
__global__ void scanA_kernel(const int* __restrict__ counts,
                             int* __restrict__ offs, int* __restrict__ bsums) {
    __shared__ int sm[SCAN_B];
    int t = threadIdx.x;
    int i = blockIdx.x * SCAN_B + t;
    int v = (i < N_NODES) ? counts[i] : 0;
    sm[t] = v;
    __syncthreads();
    for (int d = 1; d < SCAN_B; d <<= 1) {
        int add = (t >= d) ? sm[t - d] : 0;
        __syncthreads();
        sm[t] += add;
        __syncthreads();
    }
    int incl = sm[t];
    if (i < N_NODES) offs[i] = incl - v;
    if (t == SCAN_B - 1) bsums[blockIdx.x] = incl;     // inclusive block total
}

// ---------------- scan C: re-scan block sums in-block, add offsets ----------
__global__ void scanC_kernel(int* __restrict__ offs, const int* __restrict__ bsums, int total) {
    __shared__ int sb[128];
    int t = threadIdx.x;
    if (t < 128) sb[t] = (t < N_SCANBLK) ? bsums[t] : 0;
    __syncthreads();
    for (int d = 1; d < 128; d <<= 1) {
        int add = (t < 128 && t >= d) ? sb[t - d] : 0;
        __syncthreads();
        if (t < 128) sb[t] += add;
        __syncthreads();
    }
    int boff = (blockIdx.x == 0) ? 0 : sb[blockIdx.x - 1];
    int i = blockIdx.x * SCAN_B + t;
    if (i < N_NODES) offs[i] += boff;
    if (i == 0) offs[N_NODES] = total;
}

// ---------------- scatter COO -> CSR (int2 payload) --------------------------
__global__ void scatter_kernel(const int* __restrict__ rows, const int* __restrict__ cols,
                               const float* __restrict__ vals,
                               const int* __restrict__ offs, int* __restrict__ cnt,
                               int2* __restrict__ cdata, int nnz) {
    int i = blockIdx.x * blockDim.x + threadIdx.x;
    if (i >= nnz) return;
    int r = __ldcs(&rows[i]);
    int p = offs[r] + atomicSub(&cnt[r], 1) - 1;
    cdata[p] = make_int2(__ldcs(&cols[i]), __float_as_int(__ldcs(&vals[i])));
}

// ---------------- SpMM1: warp per row; ONE int4 load per nnz (R6 form) ------
__global__ void __launch_bounds__(256, 8)
spmm1_kernel(const int* __restrict__ offs, const int2* __restrict__ cdata,
             const __half* __restrict__ Wh, __half* __restrict__ xw) {
    int warp = (blockIdx.x * blockDim.x + threadIdx.x) >> 5;
    int lane = threadIdx.x & 31;
    if (warp >= N_NODES) return;

    int beg = offs[warp];
    int end = offs[warp + 1];

    float a0 = 0.f, a1 = 0.f, a2 = 0.f, a3 = 0.f;
    float a4 = 0.f, a5 = 0.f, a6 = 0.f, a7 = 0.f;

    for (int base = beg; base < end; base += 32) {
        int k = base + lane;
        int2 cv = (k < end) ? __ldcs(&cdata[k]) : make_int2(0, 0);
        int m = min(32, end - base);
        for (int t = 0; t < m; t++) {
            int   cc = __shfl_sync(0xffffffffu, cv.x, t);
            float vv = __int_as_float(__shfl_sync(0xffffffffu, cv.y, t));
            int4 wv = __ldg(reinterpret_cast<const int4*>(Wh + (size_t)cc * OUT_DIM) + lane);
            float2 f0 = __half22float2(*reinterpret_cast<__half2*>(&wv.x));
            float2 f1 = __half22float2(*reinterpret_cast<__half2*>(&wv.y));
            float2 f2 = __half22float2(*reinterpret_cast<__half2*>(&wv.z));
            float2 f3 = __half22float2(*reinterpret_cast<__half2*>(&wv.w));
            a0 = fmaf(vv, f0.x, a0); a1 = fmaf(vv, f0.y, a1);
            a2 = fmaf(vv, f1.x, a2); a3 = fmaf(vv, f1.y, a3);
            a4 = fmaf(vv, f2.x, a4); a5 = fmaf(vv, f2.y, a5);
            a6 = fmaf(vv, f3.x, a6); a7 = fmaf(vv, f3.y, a7);
        }
    }

    int4 o;
    __half2 h0 = __floats2half2_rn(a0, a1);
    __half2 h1 = __floats2half2_rn(a2, a3);
    __half2 h2 = __floats2half2_rn(a4, a5);
    __half2 h3 = __floats2half2_rn(a6, a7);
    o.x = *reinterpret_cast<int*>(&h0);
    o.y = *reinterpret_cast<int*>(&h1);
    o.z = *reinterpret_cast<int*>(&h2);
    o.w = *reinterpret_cast<int*>(&h3);
    reinterpret_cast<int4*>(xw + (size_t)warp * OUT_DIM)[lane] = o;
}

// ---------------- SpMM2 + ReLU: streaming stores protect xw in L2 -----------
__global__ void __launch_bounds__(256, 8)
spmm2_kernel(const int* __restrict__ offs, const int2* __restrict__ cdata,
             const __half* __restrict__ xw, float* __restrict__ out) {
    int warp = (blockIdx.x * blockDim.x + threadIdx.x) >> 5;
    int lane = threadIdx.x & 31;
    if (warp >= N_NODES) return;

    int beg = offs[warp];
    int end = offs[warp + 1];

    float a0 = 0.f, a1 = 0.f, a2 = 0.f, a3 = 0.f;
    float a4 = 0.f, a5 = 0.f, a6 = 0.f, a7 = 0.f;

    for (int base = beg; base < end; base += 32) {
        int k = base + lane;
        int2 cv = (k < end) ? __ldcs(&cdata[k]) : make_int2(0, 0);
        int m = min(32, end - base);
        for (int t = 0; t < m; t++) {
            int   cc = __shfl_sync(0xffffffffu, cv.x, t);
            float vv = __int_as_float(__shfl_sync(0xffffffffu, cv.y, t));
            int4 wv = __ldg(reinterpret_cast<const int4*>(xw + (size_t)cc * OUT_DIM) + lane);
            float2 f0 = __half22float2(*reinterpret_cast<__half2*>(&wv.x));
            float2 f1 = __half22float2(*reinterpret_cast<__half2*>(&wv.y));
            float2 f2 = __half22float2(*reinterpret_cast<__half2*>(&wv.z));
            float2 f3 = __half22float2(*reinterpret_cast<__half2*>(&wv.w));
            a0 = fmaf(vv, f0.x, a0); a1 = fmaf(vv, f0.y, a1);
            a2 = fmaf(vv, f1.x, a2); a3 = fmaf(vv, f1.y, a3);
            a4 = fmaf(vv, f2.x, a4); a5 = fmaf(vv, f2.y, a5);
            a6 = fmaf(vv, f3.x, a6); a7 = fmaf(vv, f3.y, a7);
        }
    }

    float4* d = reinterpret_cast<float4*>(out + (size_t)warp * OUT_DIM) + lane * 2;
    __stcs(d,     make_float4(fmaxf(a0, 0.f), fmaxf(a1, 0.f), fmaxf(a2, 0.f), fmaxf(a3, 0.f)));
    __stcs(d + 1, make_float4(fmaxf(a4, 0.f), fmaxf(a5, 0.f), fmaxf(a6, 0.f), fmaxf(a7, 0.f)));
}

// ---------------------------------------------------------------------------
extern "C" void kernel_launch(void* const* d_in, const int* in_sizes, int n_in,
                              void* d_out, int out_size) {
    const int*   x_rows   = (const int*)  d_in[0];
    const int*   x_cols   = (const int*)  d_in[1];
    const float* x_vals   = (const float*)d_in[2];
    const int*   adj_rows = (const int*)  d_in[3];
    const int*   adj_cols = (const int*)  d_in[4];
    const float* adj_vals = (const float*)d_in[5];
    const float* W        = (const float*)d_in[6];
    float*       out      = (float*)d_out;

    __half *xw, *Wh; int *cntx, *cnta, *ox, *oa, *bx, *ba; int2 *cx, *ca;
    cudaGetSymbolAddress((void**)&xw,   g_xw);
    cudaGetSymbolAddress((void**)&Wh,   g_wh);
    cudaGetSymbolAddress((void**)&cntx, g_counts_x);
    cudaGetSymbolAddress((void**)&cnta, g_counts_a);
    cudaGetSymbolAddress((void**)&ox,   g_offs_x);
    cudaGetSymbolAddress((void**)&oa,   g_offs_a);
    cudaGetSymbolAddress((void**)&bx,   g_bsums_x);
    cudaGetSymbolAddress((void**)&ba,   g_bsums_a);
    cudaGetSymbolAddress((void**)&cx,   g_cx);
    cudaGetSymbolAddress((void**)&ca,   g_ca);

    // Side stream + events: created once on first (uncaptured) call, reused.
    static cudaStream_t s2 = nullptr;
    static cudaEvent_t  evFork = nullptr, evJoin = nullptr, evW = nullptr;
    if (s2 == nullptr) {
        cudaStreamCreateWithFlags(&s2, cudaStreamNonBlocking);
        cudaEventCreateWithFlags(&evFork, cudaEventDisableTiming);
        cudaEventCreateWithFlags(&evJoin, cudaEventDisableTiming);
        cudaEventCreateWithFlags(&evW,    cudaEventDisableTiming);
    }

    const int nnz_blocks = (NNZ_X + 255) / 256;

    // ---- fork (counters are self-zeroed; no zero pass needed) ----
    cudaEventRecord(evFork, 0);
    cudaStreamWaitEvent(s2, evFork, 0);

    // ---- chain B (W convert + adj build) on side stream ----
    wcvt_kernel<<<(IN_DIM * OUT_DIM / 2 + 255) / 256, 256, 0, s2>>>(W, Wh);
    cudaEventRecord(evW, s2);                       // spmm1 depends on Wh
    hist_kernel<<<nnz_blocks, 256, 0, s2>>>(adj_rows, cnta, NNZ_ADJ);
    scanA_kernel<<<N_SCANBLK, SCAN_B, 0, s2>>>(cnta, oa, ba);
    scanC_kernel<<<N_SCANBLK, SCAN_B, 0, s2>>>(oa, ba, NNZ_ADJ);
    scatter_kernel<<<nnz_blocks, 256, 0, s2>>>(adj_rows, adj_cols, adj_vals,
                                               oa, cnta, ca, NNZ_ADJ);
    cudaEventRecord(evJoin, s2);

    // ---- chain A (x build + spmm1) on main stream ----
    hist_kernel<<<nnz_blocks, 256>>>(x_rows, cntx, NNZ_X);
    scanA_kernel<<<N_SCANBLK, SCAN_B>>>(cntx, ox, bx);
    scanC_kernel<<<N_SCANBLK, SCAN_B>>>(ox, bx, NNZ_X);
    scatter_kernel<<<nnz_blocks, 256>>>(x_rows, x_cols, x_vals,
                                        ox, cntx, cx, NNZ_X);

    cudaStreamWaitEvent(0, evW, 0);                 // ensure Wh ready
    const int spmm_blocks = (N_NODES * 32 + 255) / 256;   // warp per row
    spmm1_kernel<<<spmm_blocks, 256>>>(ox, cx, Wh, xw);

    // ---- join, then SpMM2 + ReLU ----
    cudaStreamWaitEvent(0, evJoin, 0);
    spmm2_kernel<<<spmm_blocks, 256>>>(oa, ca, xw, out);
}

// round 9
// speedup vs baseline: 1.1440x; 1.0673x over previous
#include <cuda_runtime.h>
#include <cuda_fp16.h>

#define N_NODES 100000
#define IN_DIM  1024
#define OUT_DIM 256
#define NNZ_X   3200000
#define NNZ_ADJ 3200000

#define SCAN_B    1024
#define N_SCANBLK ((N_NODES + SCAN_B - 1) / SCAN_B)   // 98

// ---------------- scratch (__device__ globals; no allocs allowed) ----------
__device__ __half g_xw[(size_t)N_NODES * OUT_DIM];     // 51.2 MB (L2-resident)
__device__ __half g_wh[IN_DIM * OUT_DIM];              // 512 KB

// Counters rely on zero-init at module load + self-restoring property:
// hist adds each node's count, scatter atomicSub's it back to exactly 0.
__device__ int   g_counts_x[N_NODES];
__device__ int   g_counts_a[N_NODES];
__device__ int   g_offs_x[N_NODES + 1];
__device__ int   g_offs_a[N_NODES + 1];
__device__ int   g_bsums_x[N_SCANBLK];
__device__ int   g_bsums_a[N_SCANBLK];
__device__ int   g_cx[NNZ_X];                          // packed (col<<16)|fp16
__device__ int   g_ca[NNZ_ADJ];                        // packed (col<<15)|q15

// ---------------- W fp32 -> fp16 -------------------------------------------
__global__ void wcvt_kernel(const float* __restrict__ W, __half* __restrict__ Wh) {
    int i = blockIdx.x * blockDim.x + threadIdx.x;      // over float2 pairs
    if (i < IN_DIM * OUT_DIM / 2) {
        float2 w = __ldcs(reinterpret_cast<const float2*>(W) + i);
        reinterpret_cast<__half2*>(Wh)[i] = __floats2half2_rn(w.x, w.y);
    }
}

// ---------------- histogram of one row array --------------------------------
__global__ void hist_kernel(const int* __restrict__ rows, int* __restrict__ counts, int nnz) {
    int i = blockIdx.x * blockDim.x + threadIdx.x;
    if (i < nnz) atomicAdd(&counts[__ldcs(&rows[i])], 1);
}

// ---------------- scan A: per-block exclusive scan --------------------------
__global__ void scanA_kernel(const int* __restrict__ counts,
                             int* __restrict__ offs, int* __restrict__ bsums) {
    __shared__ int sm[SCAN_B];
    int t = threadIdx.x;
    int i = blockIdx.x * SCAN_B + t;
    int v = (i < N_NODES) ? counts[i] : 0;
    sm[t] = v;
    __syncthreads();
    for (int d = 1; d < SCAN_B; d <<= 1) {
        int add = (t >= d) ? sm[t - d] : 0;
        __syncthreads();
        sm[t] += add;
        __syncthreads();
    }
    int incl = sm[t];
    if (i < N_NODES) offs[i] = incl - v;
    if (t == SCAN_B - 1) bsums[blockIdx.x] = incl;     // inclusive block total
}

// ---------------- scan C: re-scan block sums in-block, add offsets ----------
__global__ void scanC_kernel(int* __restrict__ offs, const int* __restrict__ bsums, int total) {
    __shared__ int sb[128];
    int t = threadIdx.x;
    if (t < 128) sb[t] = (t < N_SCANBLK) ? bsums[t] : 0;
    __syncthreads();
    for (int d = 1; d < 128; d <<= 1) {
        int add = (t < 128 && t >= d) ? sb[t - d] : 0;
        __syncthreads();
        if (t < 128) sb[t] += add;
        __syncthreads();
    }
    int boff = (blockIdx.x == 0) ? 0 : sb[blockIdx.x - 1];
    int i = blockIdx.x * SCAN_B + t;
    if (i < N_NODES) offs[i] += boff;
    if (i == 0) offs[N_NODES] = total;
}

// ---------------- scatter COO -> CSR, packed payload -------------------------
// MODE 0 (x):   col < 1024   -> p = (col<<16) | fp16(val) bits
// MODE 1 (adj): col < 2^17, val in [0,1) -> p = (col<<15) | round(val*32768) clamped
template <int MODE>
__global__ void scatter_kernel(const int* __restrict__ rows, const int* __restrict__ cols,
                               const float* __restrict__ vals,
                               const int* __restrict__ offs, int* __restrict__ cnt,
                               int* __restrict__ cdata, int nnz) {
    int i = blockIdx.x * blockDim.x + threadIdx.x;
    if (i >= nnz) return;
    int r = __ldcs(&rows[i]);
    int c = __ldcs(&cols[i]);
    float v = __ldcs(&vals[i]);
    int p = offs[r] + atomicSub(&cnt[r], 1) - 1;
    int packed;
    if (MODE == 0) {
        packed = (c << 16) | (int)__half_as_ushort(__float2half_rn(v));
    } else {
        int q = __float2int_rn(v * 32768.f);
        q = min(q, 32767);
        packed = (c << 15) | q;
    }
    cdata[p] = packed;
}

// ---------------- SpMM1: warp per row; ONE int4 gather per nnz --------------
__global__ void __launch_bounds__(256, 8)
spmm1_kernel(const int* __restrict__ offs, const int* __restrict__ cdata,
             const __half* __restrict__ Wh, __half* __restrict__ xw) {
    int warp = (blockIdx.x * blockDim.x + threadIdx.x) >> 5;
    int lane = threadIdx.x & 31;
    if (warp >= N_NODES) return;

    int beg = offs[warp];
    int end = offs[warp + 1];

    float a0 = 0.f, a1 = 0.f, a2 = 0.f, a3 = 0.f;
    float a4 = 0.f, a5 = 0.f, a6 = 0.f, a7 = 0.f;

    for (int base = beg; base < end; base += 32) {
        int k = base + lane;
        int pk = (k < end) ? __ldcs(&cdata[k]) : 0;
        int m = min(32, end - base);
#pragma unroll 4
        for (int t = 0; t < m; t++) {
            int p = __shfl_sync(0xffffffffu, pk, t);
            int cc = ((unsigned)p) >> 16;
            float vv = __half2float(__ushort_as_half((unsigned short)(p & 0xffff)));
            int4 wv = __ldg(reinterpret_cast<const int4*>(Wh + (size_t)cc * OUT_DIM) + lane);
            float2 f0 = __half22float2(*reinterpret_cast<__half2*>(&wv.x));
            float2 f1 = __half22float2(*reinterpret_cast<__half2*>(&wv.y));
            float2 f2 = __half22float2(*reinterpret_cast<__half2*>(&wv.z));
            float2 f3 = __half22float2(*reinterpret_cast<__half2*>(&wv.w));
            a0 = fmaf(vv, f0.x, a0); a1 = fmaf(vv, f0.y, a1);
            a2 = fmaf(vv, f1.x, a2); a3 = fmaf(vv, f1.y, a3);
            a4 = fmaf(vv, f2.x, a4); a5 = fmaf(vv, f2.y, a5);
            a6 = fmaf(vv, f3.x, a6); a7 = fmaf(vv, f3.y, a7);
        }
    }

    int4 o;
    __half2 h0 = __floats2half2_rn(a0, a1);
    __half2 h1 = __floats2half2_rn(a2, a3);
    __half2 h2 = __floats2half2_rn(a4, a5);
    __half2 h3 = __floats2half2_rn(a6, a7);
    o.x = *reinterpret_cast<int*>(&h0);
    o.y = *reinterpret_cast<int*>(&h1);
    o.z = *reinterpret_cast<int*>(&h2);
    o.w = *reinterpret_cast<int*>(&h3);
    reinterpret_cast<int4*>(xw + (size_t)warp * OUT_DIM)[lane] = o;
}

// ---------------- SpMM2 + ReLU: streaming stores protect xw in L2 -----------
__global__ void __launch_bounds__(256, 8)
spmm2_kernel(const int* __restrict__ offs, const int* __restrict__ cdata,
             const __half* __restrict__ xw, float* __restrict__ out) {
    int warp = (blockIdx.x * blockDim.x + threadIdx.x) >> 5;
    int lane = threadIdx.x & 31;
    if (warp >= N_NODES) return;

    int beg = offs[warp];
    int end = offs[warp + 1];

    float a0 = 0.f, a1 = 0.f, a2 = 0.f, a3 = 0.f;
    float a4 = 0.f, a5 = 0.f, a6 = 0.f, a7 = 0.f;

    const float QINV = 1.f / 32768.f;

    for (int base = beg; base < end; base += 32) {
        int k = base + lane;
        int pk = (k < end) ? __ldcs(&cdata[k]) : 0;
        int m = min(32, end - base);
#pragma unroll 4
        for (int t = 0; t < m; t++) {
            int p = __shfl_sync(0xffffffffu, pk, t);
            int cc = ((unsigned)p) >> 15;
            float vv = (float)(p & 0x7fff) * QINV;
            int4 wv = __ldg(reinterpret_cast<const int4*>(xw + (size_t)cc * OUT_DIM) + lane);
            float2 f0 = __half22float2(*reinterpret_cast<__half2*>(&wv.x));
            float2 f1 = __half22float2(*reinterpret_cast<__half2*>(&wv.y));
            float2 f2 = __half22float2(*reinterpret_cast<__half2*>(&wv.z));
            float2 f3 = __half22float2(*reinterpret_cast<__half2*>(&wv.w));
            a0 = fmaf(vv, f0.x, a0); a1 = fmaf(vv, f0.y, a1);
            a2 = fmaf(vv, f1.x, a2); a3 = fmaf(vv, f1.y, a3);
            a4 = fmaf(vv, f2.x, a4); a5 = fmaf(vv, f2.y, a5);
            a6 = fmaf(vv, f3.x, a6); a7 = fmaf(vv, f3.y, a7);
        }
    }

    float4* d = reinterpret_cast<float4*>(out + (size_t)warp * OUT_DIM) + lane * 2;
    __stcs(d,     make_float4(fmaxf(a0, 0.f), fmaxf(a1, 0.f), fmaxf(a2, 0.f), fmaxf(a3, 0.f)));
    __stcs(d + 1, make_float4(fmaxf(a4, 0.f), fmaxf(a5, 0.f), fmaxf(a6, 0.f), fmaxf(a7, 0.f)));
}

// ---------------------------------------------------------------------------
extern "C" void kernel_launch(void* const* d_in, const int* in_sizes, int n_in,
                              void* d_out, int out_size) {
    const int*   x_rows   = (const int*)  d_in[0];
    const int*   x_cols   = (const int*)  d_in[1];
    const float* x_vals   = (const float*)d_in[2];
    const int*   adj_rows = (const int*)  d_in[3];
    const int*   adj_cols = (const int*)  d_in[4];
    const float* adj_vals = (const float*)d_in[5];
    const float* W        = (const float*)d_in[6];
    float*       out      = (float*)d_out;

    __half *xw, *Wh; int *cntx, *cnta, *ox, *oa, *bx, *ba, *cx, *ca;
    cudaGetSymbolAddress((void**)&xw,   g_xw);
    cudaGetSymbolAddress((void**)&Wh,   g_wh);
    cudaGetSymbolAddress((void**)&cntx, g_counts_x);
    cudaGetSymbolAddress((void**)&cnta, g_counts_a);
    cudaGetSymbolAddress((void**)&ox,   g_offs_x);
    cudaGetSymbolAddress((void**)&oa,   g_offs_a);
    cudaGetSymbolAddress((void**)&bx,   g_bsums_x);
    cudaGetSymbolAddress((void**)&ba,   g_bsums_a);
    cudaGetSymbolAddress((void**)&cx,   g_cx);
    cudaGetSymbolAddress((void**)&ca,   g_ca);

    // Side stream + events: created once on first (uncaptured) call, reused.
    static cudaStream_t s2 = nullptr;
    static cudaEvent_t  evFork = nullptr, evJoin = nullptr, evW = nullptr;
    if (s2 == nullptr) {
        cudaStreamCreateWithFlags(&s2, cudaStreamNonBlocking);
        cudaEventCreateWithFlags(&evFork, cudaEventDisableTiming);
        cudaEventCreateWithFlags(&evJoin, cudaEventDisableTiming);
        cudaEventCreateWithFlags(&evW,    cudaEventDisableTiming);
    }

    const int nnz_blocks = (NNZ_X + 255) / 256;

    // ---- fork (counters are self-zeroed; no zero pass needed) ----
    cudaEventRecord(evFork, 0);
    cudaStreamWaitEvent(s2, evFork, 0);

    // ---- chain B (W convert + adj build) on side stream ----
    wcvt_kernel<<<(IN_DIM * OUT_DIM / 2 + 255) / 256, 256, 0, s2>>>(W, Wh);
    cudaEventRecord(evW, s2);                       // spmm1 depends on Wh
    hist_kernel<<<nnz_blocks, 256, 0, s2>>>(adj_rows, cnta, NNZ_ADJ);
    scanA_kernel<<<N_SCANBLK, SCAN_B, 0, s2>>>(cnta, oa, ba);
    scanC_kernel<<<N_SCANBLK, SCAN_B, 0, s2>>>(oa, ba, NNZ_ADJ);
    scatter_kernel<1><<<nnz_blocks, 256, 0, s2>>>(adj_rows, adj_cols, adj_vals,
                                                  oa, cnta, ca, NNZ_ADJ);
    cudaEventRecord(evJoin, s2);

    // ---- chain A (x build + spmm1) on main stream ----
    hist_kernel<<<nnz_blocks, 256>>>(x_rows, cntx, NNZ_X);
    scanA_kernel<<<N_SCANBLK, SCAN_B>>>(cntx, ox, bx);
    scanC_kernel<<<N_SCANBLK, SCAN_B>>>(ox, bx, NNZ_X);
    scatter_kernel<0><<<nnz_blocks, 256>>>(x_rows, x_cols, x_vals,
                                           ox, cntx, cx, NNZ_X);

    cudaStreamWaitEvent(0, evW, 0);                 // ensure Wh ready
    const int spmm_blocks = (N_NODES * 32 + 255) / 256;   // warp per row
    spmm1_kernel<<<spmm_blocks, 256>>>(ox, cx, Wh, xw);

    // ---- join, then SpMM2 + ReLU ----
    cudaStreamWaitEvent(0, evJoin, 0);
    spmm2_kernel<<<spmm_blocks, 256>>>(oa, ca, xw, out);
}

// round 10
// speedup vs baseline: 1.1910x; 1.0410x over previous
#include <cuda_runtime.h>
#include <cuda_fp16.h>

#define N_NODES 100000
#define IN_DIM  1024
#define OUT_DIM 256
#define NNZ_X   3200000
#define NNZ_ADJ 3200000

#define SCAN_B    1024
#define N_SCANBLK ((N_NODES + SCAN_B - 1) / SCAN_B)   // 98

// ---------------- scratch (__device__ globals; no allocs allowed) ----------
__device__ __half g_xw[(size_t)N_NODES * OUT_DIM];     // 51.2 MB (L2-resident)
__device__ __half g_wh[IN_DIM * OUT_DIM];              // 512 KB

// Counters rely on zero-init at module load + self-restoring property:
// hist adds each node's count, scatter atomicSub's it back to exactly 0.
__device__ int   g_counts_x[N_NODES];
__device__ int   g_counts_a[N_NODES];
__device__ int   g_offs_x[N_NODES + 1];
__device__ int   g_offs_a[N_NODES + 1];
__device__ int   g_bsums_x[N_SCANBLK];
__device__ int   g_bsums_a[N_SCANBLK];
__device__ int   g_cx[NNZ_X];                          // packed (col<<16)|fp16
__device__ int   g_ca[NNZ_ADJ];                        // packed (col<<15)|q15

// ---------------- mixed-precision FMA: fp16 x fp16 -> fp32 accum ------------
// fma.rn.f32.f16 (PTX ISA 8.6+, sm_100): kills the F2F converts.
__device__ __forceinline__ void fma_h2(float& s0, float& s1, int wpair, unsigned short vh) {
    unsigned short h0, h1;
    asm("mov.b32 {%0, %1}, %2;" : "=h"(h0), "=h"(h1) : "r"(wpair));
    asm("fma.rn.f32.f16 %0, %1, %2, %0;" : "+f"(s0) : "h"(h0), "h"(vh));
    asm("fma.rn.f32.f16 %0, %1, %2, %0;" : "+f"(s1) : "h"(h1), "h"(vh));
}

// ---------------- W fp32 -> fp16 -------------------------------------------
__global__ void wcvt_kernel(const float* __restrict__ W, __half* __restrict__ Wh) {
    int i = blockIdx.x * blockDim.x + threadIdx.x;      // over float2 pairs
    if (i < IN_DIM * OUT_DIM / 2) {
        float2 w = __ldcs(reinterpret_cast<const float2*>(W) + i);
        reinterpret_cast<__half2*>(Wh)[i] = __floats2half2_rn(w.x, w.y);
    }
}

// ---------------- histogram of one row array --------------------------------
__global__ void hist_kernel(const int* __restrict__ rows, int* __restrict__ counts, int nnz) {
    int i = blockIdx.x * blockDim.x + threadIdx.x;
    if (i < nnz) atomicAdd(&counts[__ldcs(&rows[i])], 1);
}

// ---------------- scan A: per-block exclusive scan --------------------------
__global__ void scanA_kernel(const int* __restrict__ counts,
                             int* __restrict__ offs, int* __restrict__ bsums) {
    __shared__ int sm[SCAN_B];
    int t = threadIdx.x;
    int i = blockIdx.x * SCAN_B + t;
    int v = (i < N_NODES) ? counts[i] : 0;
    sm[t] = v;
    __syncthreads();
    for (int d = 1; d < SCAN_B; d <<= 1) {
        int add = (t >= d) ? sm[t - d] : 0;
        __syncthreads();
        sm[t] += add;
        __syncthreads();
    }
    int incl = sm[t];
    if (i < N_NODES) offs[i] = incl - v;
    if (t == SCAN_B - 1) bsums[blockIdx.x] = incl;     // inclusive block total
}

// ---------------- scan C: re-scan block sums in-block, add offsets ----------
__global__ void scanC_kernel(int* __restrict__ offs, const int* __restrict__ bsums, int total) {
    __shared__ int sb[128];
    int t = threadIdx.x;
    if (t < 128) sb[t] = (t < N_SCANBLK) ? bsums[t] : 0;
    __syncthreads();
    for (int d = 1; d < 128; d <<= 1) {
        int add = (t < 128 && t >= d) ? sb[t - d] : 0;
        __syncthreads();
        if (t < 128) sb[t] += add;
        __syncthreads();
    }
    int boff = (blockIdx.x == 0) ? 0 : sb[blockIdx.x - 1];
    int i = blockIdx.x * SCAN_B + t;
    if (i < N_NODES) offs[i] += boff;
    if (i == 0) offs[N_NODES] = total;
}

// ---------------- scatter COO -> CSR, packed payload -------------------------
// MODE 0 (x):   col < 1024   -> p = (col<<16) | fp16(val) bits
// MODE 1 (adj): col < 2^17, val in [0,1) -> p = (col<<15) | round(val*32768) clamped
template <int MODE>
__global__ void scatter_kernel(const int* __restrict__ rows, const int* __restrict__ cols,
                               const float* __restrict__ vals,
                               const int* __restrict__ offs, int* __restrict__ cnt,
                               int* __restrict__ cdata, int nnz) {
    int i = blockIdx.x * blockDim.x + threadIdx.x;
    if (i >= nnz) return;
    int r = __ldcs(&rows[i]);
    int c = __ldcs(&cols[i]);
    float v = __ldcs(&vals[i]);
    int p = offs[r] + atomicSub(&cnt[r], 1) - 1;
    int packed;
    if (MODE == 0) {
        packed = (c << 16) | (int)__half_as_ushort(__float2half_rn(v));
    } else {
        int q = __float2int_rn(v * 32768.f);
        q = min(q, 32767);
        packed = (c << 15) | q;
    }
    cdata[p] = packed;
}

// ---------------- SpMM1: warp per row; ONE int4 gather + mixed FMA ----------
__global__ void __launch_bounds__(256, 8)
spmm1_kernel(const int* __restrict__ offs, const int* __restrict__ cdata,
             const __half* __restrict__ Wh, __half* __restrict__ xw) {
    int warp = (blockIdx.x * blockDim.x + threadIdx.x) >> 5;
    int lane = threadIdx.x & 31;
    if (warp >= N_NODES) return;

    int beg = offs[warp];
    int end = offs[warp + 1];

    float a0 = 0.f, a1 = 0.f, a2 = 0.f, a3 = 0.f;
    float a4 = 0.f, a5 = 0.f, a6 = 0.f, a7 = 0.f;

    for (int base = beg; base < end; base += 32) {
        int k = base + lane;
        int pk = (k < end) ? __ldcs(&cdata[k]) : 0;
        int m = min(32, end - base);
#pragma unroll 8
        for (int t = 0; t < m; t++) {
            int p = __shfl_sync(0xffffffffu, pk, t);
            int cc = ((unsigned)p) >> 16;
            unsigned short vh = (unsigned short)(p & 0xffff);   // fp16 bits
            int4 wv = __ldg(reinterpret_cast<const int4*>(Wh + (size_t)cc * OUT_DIM) + lane);
            fma_h2(a0, a1, wv.x, vh);
            fma_h2(a2, a3, wv.y, vh);
            fma_h2(a4, a5, wv.z, vh);
            fma_h2(a6, a7, wv.w, vh);
        }
    }

    int4 o;
    __half2 h0 = __floats2half2_rn(a0, a1);
    __half2 h1 = __floats2half2_rn(a2, a3);
    __half2 h2 = __floats2half2_rn(a4, a5);
    __half2 h3 = __floats2half2_rn(a6, a7);
    o.x = *reinterpret_cast<int*>(&h0);
    o.y = *reinterpret_cast<int*>(&h1);
    o.z = *reinterpret_cast<int*>(&h2);
    o.w = *reinterpret_cast<int*>(&h3);
    reinterpret_cast<int4*>(xw + (size_t)warp * OUT_DIM)[lane] = o;
}

// ---------------- SpMM2 + ReLU: streaming stores protect xw in L2 -----------
__global__ void __launch_bounds__(256, 8)
spmm2_kernel(const int* __restrict__ offs, const int* __restrict__ cdata,
             const __half* __restrict__ xw, float* __restrict__ out) {
    int warp = (blockIdx.x * blockDim.x + threadIdx.x) >> 5;
    int lane = threadIdx.x & 31;
    if (warp >= N_NODES) return;

    int beg = offs[warp];
    int end = offs[warp + 1];

    float a0 = 0.f, a1 = 0.f, a2 = 0.f, a3 = 0.f;
    float a4 = 0.f, a5 = 0.f, a6 = 0.f, a7 = 0.f;

    const float QINV = 1.f / 32768.f;

    for (int base = beg; base < end; base += 32) {
        int k = base + lane;
        int pk = (k < end) ? __ldcs(&cdata[k]) : 0;
        int m = min(32, end - base);
#pragma unroll 8
        for (int t = 0; t < m; t++) {
            int p = __shfl_sync(0xffffffffu, pk, t);
            int cc = ((unsigned)p) >> 15;
            float vv = (float)(p & 0x7fff) * QINV;
            int4 wv = __ldg(reinterpret_cast<const int4*>(xw + (size_t)cc * OUT_DIM) + lane);
            float2 f0 = __half22float2(*reinterpret_cast<__half2*>(&wv.x));
            float2 f1 = __half22float2(*reinterpret_cast<__half2*>(&wv.y));
            float2 f2 = __half22float2(*reinterpret_cast<__half2*>(&wv.z));
            float2 f3 = __half22float2(*reinterpret_cast<__half2*>(&wv.w));
            a0 = fmaf(vv, f0.x, a0); a1 = fmaf(vv, f0.y, a1);
            a2 = fmaf(vv, f1.x, a2); a3 = fmaf(vv, f1.y, a3);
            a4 = fmaf(vv, f2.x, a4); a5 = fmaf(vv, f2.y, a5);
            a6 = fmaf(vv, f3.x, a6); a7 = fmaf(vv, f3.y, a7);
        }
    }

    float4* d = reinterpret_cast<float4*>(out + (size_t)warp * OUT_DIM) + lane * 2;
    __stcs(d,     make_float4(fmaxf(a0, 0.f), fmaxf(a1, 0.f), fmaxf(a2, 0.f), fmaxf(a3, 0.f)));
    __stcs(d + 1, make_float4(fmaxf(a4, 0.f), fmaxf(a5, 0.f), fmaxf(a6, 0.f), fmaxf(a7, 0.f)));
}

// ---------------------------------------------------------------------------
extern "C" void kernel_launch(void* const* d_in, const int* in_sizes, int n_in,
                              void* d_out, int out_size) {
    const int*   x_rows   = (const int*)  d_in[0];
    const int*   x_cols   = (const int*)  d_in[1];
    const float* x_vals   = (const float*)d_in[2];
    const int*   adj_rows = (const int*)  d_in[3];
    const int*   adj_cols = (const int*)  d_in[4];
    const float* adj_vals = (const float*)d_in[5];
    const float* W        = (const float*)d_in[6];
    float*       out      = (float*)d_out;

    __half *xw, *Wh; int *cntx, *cnta, *ox, *oa, *bx, *ba, *cx, *ca;
    cudaGetSymbolAddress((void**)&xw,   g_xw);
    cudaGetSymbolAddress((void**)&Wh,   g_wh);
    cudaGetSymbolAddress((void**)&cntx, g_counts_x);
    cudaGetSymbolAddress((void**)&cnta, g_counts_a);
    cudaGetSymbolAddress((void**)&ox,   g_offs_x);
    cudaGetSymbolAddress((void**)&oa,   g_offs_a);
    cudaGetSymbolAddress((void**)&bx,   g_bsums_x);
    cudaGetSymbolAddress((void**)&ba,   g_bsums_a);
    cudaGetSymbolAddress((void**)&cx,   g_cx);
    cudaGetSymbolAddress((void**)&ca,   g_ca);

    // Side stream + events: created once on first (uncaptured) call, reused.
    static cudaStream_t s2 = nullptr;
    static cudaEvent_t  evFork = nullptr, evJoin = nullptr, evW = nullptr;
    if (s2 == nullptr) {
        cudaStreamCreateWithFlags(&s2, cudaStreamNonBlocking);
        cudaEventCreateWithFlags(&evFork, cudaEventDisableTiming);
        cudaEventCreateWithFlags(&evJoin, cudaEventDisableTiming);
        cudaEventCreateWithFlags(&evW,    cudaEventDisableTiming);
    }

    const int nnz_blocks = (NNZ_X + 255) / 256;

    // ---- fork (counters are self-zeroed; no zero pass needed) ----
    cudaEventRecord(evFork, 0);
    cudaStreamWaitEvent(s2, evFork, 0);

    // ---- chain B (W convert + adj build) on side stream ----
    wcvt_kernel<<<(IN_DIM * OUT_DIM / 2 + 255) / 256, 256, 0, s2>>>(W, Wh);
    cudaEventRecord(evW, s2);                       // spmm1 depends on Wh
    hist_kernel<<<nnz_blocks, 256, 0, s2>>>(adj_rows, cnta, NNZ_ADJ);
    scanA_kernel<<<N_SCANBLK, SCAN_B, 0, s2>>>(cnta, oa, ba);
    scanC_kernel<<<N_SCANBLK, SCAN_B, 0, s2>>>(oa, ba, NNZ_ADJ);
    scatter_kernel<1><<<nnz_blocks, 256, 0, s2>>>(adj_rows, adj_cols, adj_vals,
                                                  oa, cnta, ca, NNZ_ADJ);
    cudaEventRecord(evJoin, s2);

    // ---- chain A (x build + spmm1) on main stream ----
    hist_kernel<<<nnz_blocks, 256>>>(x_rows, cntx, NNZ_X);
    scanA_kernel<<<N_SCANBLK, SCAN_B>>>(cntx, ox, bx);
    scanC_kernel<<<N_SCANBLK, SCAN_B>>>(ox, bx, NNZ_X);
    scatter_kernel<0><<<nnz_blocks, 256>>>(x_rows, x_cols, x_vals,
                                           ox, cntx, cx, NNZ_X);

    cudaStreamWaitEvent(0, evW, 0);                 // ensure Wh ready
    const int spmm_blocks = (N_NODES * 32 + 255) / 256;   // warp per row
    spmm1_kernel<<<spmm_blocks, 256>>>(ox, cx, Wh, xw);

    // ---- join, then SpMM2 + ReLU ----
    cudaStreamWaitEvent(0, evJoin, 0);
    spmm2_kernel<<<spmm_blocks, 256>>>(oa, ca, xw, out);
}